// round 13
// baseline (speedup 1.0000x reference)
#include <cuda_runtime.h>
#include <math.h>

#define N_NODES 100000
#define N_EDGES 6400000
#define F_IN    128
#define F_OUT   16

// ------------- device scratch (zero-init; invariants restored per call) ---
__device__ int   g_deg [N_NODES];            // in-deg from 0; k_dinv resets
__device__ float g_dinv[N_NODES];            // rsqrt(deg+1)
__device__ float g_g   [N_NODES * F_OUT];    // h=x@W (unscaled), then *dinv
__device__ float g_acc [N_NODES * F_OUT];    // scatter acc; zeroed in fused

// ---------------- K1: fused  gemm(h) || degree || zero ---------------------
// role = blockIdx&3: 0 -> gemm (391 ids, 256 nodes each, 2 nodes/thread),
// 1,2 -> degree (782 ids), 3 -> zero (391 ids).
#define GEMM_IDS 391
#define DEG_IDS  782
#define ZERO_IDS 391
#define FUSED_BLOCKS (4 * 391)                 // 1564
#define DEG_STRIDE (DEG_IDS * 128)             // 100096 threads

__global__ void __launch_bounds__(128) k_fused(const float* __restrict__ x,
                                               const float* __restrict__ W,
                                               const int* __restrict__ dst,
                                               float* __restrict__ out) {
    __shared__ float4 Ws4[F_IN * F_OUT / 4];
    int role = blockIdx.x & 3;
    int gid  = blockIdx.x >> 2;
    int tid  = threadIdx.x;

    if (role == 0) {                           // ---- GEMM role: 2 nodes/thr
        for (int i = tid; i < F_IN * F_OUT / 4; i += 128)
            Ws4[i] = ((const float4*)W)[i];
        __syncthreads();

        int n0 = gid * 256 + tid;              // always < N_NODES (99967 max)
        int n1 = n0 + 128;
        bool v1 = (n1 < N_NODES);
        int n1c = v1 ? n1 : (N_NODES - 1);     // clamped safe load address

        const float4* xa = (const float4*)(x + (size_t)n0 * F_IN);
        const float4* xb = (const float4*)(x + (size_t)n1c * F_IN);

        float4 a0 = make_float4(0.f, 0.f, 0.f, 0.f);
        float4 a1 = a0, a2 = a0, a3 = a0;
        float4 c0 = a0, c1 = a0, c2 = a0, c3 = a0;

#pragma unroll
        for (int k4 = 0; k4 < F_IN / 4; k4++) {
            float4 xva = xa[k4];
            float4 xvb = xb[k4];
#pragma unroll
            for (int j = 0; j < 4; j++) {
                float pa = (j == 0) ? xva.x : (j == 1) ? xva.y
                         : (j == 2) ? xva.z : xva.w;
                float pb = (j == 0) ? xvb.x : (j == 1) ? xvb.y
                         : (j == 2) ? xvb.z : xvb.w;
                int kb = (k4 * 4 + j) * 4;
                float4 w0 = Ws4[kb + 0];
                float4 w1 = Ws4[kb + 1];
                float4 w2 = Ws4[kb + 2];
                float4 w3 = Ws4[kb + 3];
                a0.x += pa * w0.x; a0.y += pa * w0.y;
                a0.z += pa * w0.z; a0.w += pa * w0.w;
                a1.x += pa * w1.x; a1.y += pa * w1.y;
                a1.z += pa * w1.z; a1.w += pa * w1.w;
                a2.x += pa * w2.x; a2.y += pa * w2.y;
                a2.z += pa * w2.z; a2.w += pa * w2.w;
                a3.x += pa * w3.x; a3.y += pa * w3.y;
                a3.z += pa * w3.z; a3.w += pa * w3.w;
                c0.x += pb * w0.x; c0.y += pb * w0.y;
                c0.z += pb * w0.z; c0.w += pb * w0.w;
                c1.x += pb * w1.x; c1.y += pb * w1.y;
                c1.z += pb * w1.z; c1.w += pb * w1.w;
                c2.x += pb * w2.x; c2.y += pb * w2.y;
                c2.z += pb * w2.z; c2.w += pb * w2.w;
                c3.x += pb * w3.x; c3.y += pb * w3.y;
                c3.z += pb * w3.z; c3.w += pb * w3.w;
            }
        }
        float4* ga = (float4*)(g_g + (size_t)n0 * F_OUT);
        ga[0] = a0; ga[1] = a1; ga[2] = a2; ga[3] = a3;
        if (v1) {
            float4* gb = (float4*)(g_g + (size_t)n1 * F_OUT);
            gb[0] = c0; gb[1] = c1; gb[2] = c2; gb[3] = c3;
        }
    } else if (role < 3) {                     // ---- DEGREE role ----
        int deg_id = gid * 2 + (role - 1);     // 0..781
        int e = deg_id * 128 + tid;
#pragma unroll 4
        for (; e < N_EDGES; e += DEG_STRIDE) {
            int c = dst[e];
            atomicAdd(&g_deg[c], 1);
        }
    } else {                                   // ---- ZERO role ----
        const float4 z4 = make_float4(0.f, 0.f, 0.f, 0.f);
        for (int i = gid * 128 + tid; i < N_NODES * F_OUT / 4;
             i += ZERO_IDS * 128)
            ((float4*)g_acc)[i] = z4;
        if (gid == 0 && tid < F_OUT) out[tid] = 0.0f;
    }
}

// ---------------- K2: dinv v2 (R11-proven) + PDL sync ----------------------
__global__ void __launch_bounds__(256) k_dinv() {
    cudaGridDependencySynchronize();           // wait for k_fused results
    int t = blockIdx.x * 256 + threadIdx.x;
    int n = t >> 2;
    int q = t & 3;
    if (n >= N_NODES) return;
    float dv = rsqrtf((float)(g_deg[n] + 1));  // +1 self loop
    if (q == 0) {
        g_dinv[n] = dv;
        g_deg[n] = 0;                          // restore invariant for replay
    }
    float4* gg = (float4*)g_g + n * 4 + q;
    float4 v = *gg;
    *gg = make_float4(v.x * dv, v.y * dv, v.z * dv, v.w * dv);
}

// ---------------- K3: scatter (R2-proven core) + PDL index prefetch --------
__global__ void __launch_bounds__(256) k_scatter(const int* __restrict__ src,
                                                 const int* __restrict__ dst) {
    long long t = (long long)blockIdx.x * blockDim.x + threadIdx.x;
    int e = (int)(t >> 2);
    int q = (int)(t & 3);
    if (e >= N_EDGES) {
        cudaGridDependencySynchronize();
        return;
    }
    int r = src[e];
    int c = dst[e];
    cudaGridDependencySynchronize();           // wait for k_dinv (g scaled)
    float4 v = ((const float4*)g_g)[r * 4 + q];
    float* p = g_acc + (size_t)c * F_OUT + q * 4;
    asm volatile("red.global.add.v4.f32 [%0], {%1,%2,%3,%4};"
                 :: "l"(p), "f"(v.x), "f"(v.y), "f"(v.z), "f"(v.w)
                 : "memory");
}

// ---------------- K4: finalize v2 (R10-proven) + PDL prefetch --------------
#define FIN_TPB    256
#define FIN_BLOCKS ((4 * N_NODES + FIN_TPB - 1) / FIN_TPB)   // 1563

__global__ void __launch_bounds__(FIN_TPB) k_finalize(const float* __restrict__ b,
                                                      float* __restrict__ out) {
    __shared__ float sm[F_OUT];
    if (threadIdx.x < F_OUT) sm[threadIdx.x] = 0.f;

    int t = blockIdx.x * FIN_TPB + threadIdx.x;
    int n = t >> 2;
    int q = t & 3;
    int lane = threadIdx.x & 31;

    float dv = 0.f;
    float4 g = make_float4(0.f, 0.f, 0.f, 0.f);
    float4 bb = g;
    if (n < N_NODES) {
        dv = g_dinv[n];
        g  = ((const float4*)g_g)[n * 4 + q];
        bb = ((const float4*)b)[q];
    }
    cudaGridDependencySynchronize();           // wait for k_scatter (acc)
    __syncthreads();

    float4 r = make_float4(0.f, 0.f, 0.f, 0.f);
    if (n < N_NODES) {
        float4 a = ((const float4*)g_acc)[n * 4 + q];
        r.x = tanhf(dv * (a.x + g.x) + bb.x);
        r.y = tanhf(dv * (a.y + g.y) + bb.y);
        r.z = tanhf(dv * (a.z + g.z) + bb.z);
        r.w = tanhf(dv * (a.w + g.w) + bb.w);
    }

#pragma unroll
    for (int off = 16; off >= 4; off >>= 1) {
        r.x += __shfl_xor_sync(0xFFFFFFFFu, r.x, off);
        r.y += __shfl_xor_sync(0xFFFFFFFFu, r.y, off);
        r.z += __shfl_xor_sync(0xFFFFFFFFu, r.z, off);
        r.w += __shfl_xor_sync(0xFFFFFFFFu, r.w, off);
    }
    if (lane < 4) {
        atomicAdd(&sm[lane * 4 + 0], r.x);
        atomicAdd(&sm[lane * 4 + 1], r.y);
        atomicAdd(&sm[lane * 4 + 2], r.z);
        atomicAdd(&sm[lane * 4 + 3], r.w);
    }
    __syncthreads();
    if (threadIdx.x < F_OUT)
        atomicAdd(&out[threadIdx.x], sm[threadIdx.x] * (1.0f / (float)N_NODES));
}

// ---------------- launch (PDL chain) ----------------------------------------
static void launch_pdl(void* func, dim3 grid, dim3 block,
                       void** args, cudaStream_t stream) {
    cudaLaunchAttribute attr[1];
    attr[0].id = cudaLaunchAttributeProgrammaticStreamSerialization;
    attr[0].val.programmaticStreamSerializationAllowed = 1;
    cudaLaunchConfig_t cfg;
    cfg.gridDim = grid;
    cfg.blockDim = block;
    cfg.dynamicSmemBytes = 0;
    cfg.stream = stream;
    cfg.attrs = attr;
    cfg.numAttrs = 1;
    cudaLaunchKernelExC(&cfg, func, args);
}

extern "C" void kernel_launch(void* const* d_in, const int* in_sizes, int n_in,
                              void* d_out, int out_size) {
    const float* x  = (const float*)d_in[0];
    const int*   ei = (const int*)d_in[1];   // [2, N_EDGES] int32 (JAX x64 off)
    const float* W  = (const float*)d_in[2];
    const float* b  = (const float*)d_in[3];
    float*       out = (float*)d_out;

    const int* src = ei;
    const int* dst = ei + N_EDGES;

    k_fused<<<FUSED_BLOCKS, 128>>>(x, W, dst, out);

    {   // dinv: PDL after fused
        void* args[] = {};
        launch_pdl((void*)k_dinv, dim3((4 * N_NODES + 255) / 256), dim3(256),
                   args, 0);
    }
    {   // scatter: PDL after dinv
        long long threads = (long long)N_EDGES * 4;
        void* args[] = {(void*)&src, (void*)&dst};
        launch_pdl((void*)k_scatter, dim3((int)((threads + 255) / 256)),
                   dim3(256), args, 0);
    }
    {   // finalize: PDL after scatter
        void* args[] = {(void*)&b, (void*)&out};
        launch_pdl((void*)k_finalize, dim3(FIN_BLOCKS), dim3(FIN_TPB), args, 0);
    }
}

// round 14
// speedup vs baseline: 1.0498x; 1.0498x over previous
#include <cuda_runtime.h>
#include <math.h>

#define N_NODES 100000
#define N_EDGES 6400000
#define F_IN    128
#define F_OUT   16

// ------------- device scratch (zero-init; invariants restored per call) ---
__device__ int   g_deg [N_NODES];            // in-deg from 0; k_dinv resets
__device__ float g_dinv[N_NODES];            // rsqrt(deg+1)
__device__ float g_g   [N_NODES * F_OUT];    // h=x@W (unscaled), then *dinv
__device__ float g_acc [N_NODES * F_OUT];    // scatter acc; zeroed in fused

// ---------------- K1: fused  gemm(h) || degree || zero ---------------------
// role = blockIdx%19: <16 gemm (6256 ids, 16 nodes each, warp-cooperative
// coalesced loads), <18 degree (782 ids, proven config), ==18 zero (391 ids).
#define GEMM_IDS 6256
#define DEG_IDS  782
#define ZERO_IDS 391
#define FUSED_BLOCKS (19 * 391)                // 7429
#define DEG_STRIDE (DEG_IDS * 128)             // 100096 threads

__global__ void __launch_bounds__(128) k_fused(const float* __restrict__ x,
                                               const float* __restrict__ W,
                                               const int* __restrict__ dst,
                                               float* __restrict__ out) {
    __shared__ float4 Ws4[F_IN * F_OUT / 4];   // XOR-swizzled W quads
    int role = blockIdx.x % 19;
    int gid  = blockIdx.x / 19;
    int tid  = threadIdx.x;

    if (role < 16) {                           // ---- GEMM role ----
        int gemm_id = gid * 16 + role;         // 0..6255
        // stage W swizzled: quad index i -> i ^ ((i>>4)&7)
        for (int i = tid; i < F_IN * F_OUT / 4; i += 128)
            Ws4[i ^ ((i >> 4) & 7)] = ((const float4*)W)[i];
        __syncthreads();

        int lane = tid & 31;
        int o    = lane & 7;                   // K-eighth (16 k's)
        int nw   = lane >> 3;                  // node within warp (0..3)
        int n    = gemm_id * 16 + (tid >> 5) * 4 + nw;
        bool valid = (n < N_NODES);
        int nc = valid ? n : (N_NODES - 1);

        const float4* xr = (const float4*)(x + (size_t)nc * F_IN);
        float4 A0 = make_float4(0.f, 0.f, 0.f, 0.f);
        float4 A1 = A0, A2 = A0, A3 = A0;

#pragma unroll
        for (int i = 0; i < 4; i++) {
            float4 xv = xr[i * 8 + o];         // 8 lanes -> one 128B line
#pragma unroll
            for (int j = 0; j < 4; j++) {
                float xc = (j == 0) ? xv.x : (j == 1) ? xv.y
                         : (j == 2) ? xv.z : xv.w;
                int base = (i * 32 + o * 4 + j) * 4;   // quad index of row k
                float4 w0 = Ws4[(base + 0) ^ o];       // bank-disjoint
                float4 w1 = Ws4[(base + 1) ^ o];
                float4 w2 = Ws4[(base + 2) ^ o];
                float4 w3 = Ws4[(base + 3) ^ o];
                A0.x += xc * w0.x; A0.y += xc * w0.y;
                A0.z += xc * w0.z; A0.w += xc * w0.w;
                A1.x += xc * w1.x; A1.y += xc * w1.y;
                A1.z += xc * w1.z; A1.w += xc * w1.w;
                A2.x += xc * w2.x; A2.y += xc * w2.y;
                A2.z += xc * w2.z; A2.w += xc * w2.w;
                A3.x += xc * w3.x; A3.y += xc * w3.y;
                A3.z += xc * w3.z; A3.w += xc * w3.w;
            }
        }
        // reduce over the 8 K-eighths (lane bits 0..2)
#pragma unroll
        for (int off = 1; off <= 4; off <<= 1) {
            A0.x += __shfl_xor_sync(0xFFFFFFFFu, A0.x, off);
            A0.y += __shfl_xor_sync(0xFFFFFFFFu, A0.y, off);
            A0.z += __shfl_xor_sync(0xFFFFFFFFu, A0.z, off);
            A0.w += __shfl_xor_sync(0xFFFFFFFFu, A0.w, off);
            A1.x += __shfl_xor_sync(0xFFFFFFFFu, A1.x, off);
            A1.y += __shfl_xor_sync(0xFFFFFFFFu, A1.y, off);
            A1.z += __shfl_xor_sync(0xFFFFFFFFu, A1.z, off);
            A1.w += __shfl_xor_sync(0xFFFFFFFFu, A1.w, off);
            A2.x += __shfl_xor_sync(0xFFFFFFFFu, A2.x, off);
            A2.y += __shfl_xor_sync(0xFFFFFFFFu, A2.y, off);
            A2.z += __shfl_xor_sync(0xFFFFFFFFu, A2.z, off);
            A2.w += __shfl_xor_sync(0xFFFFFFFFu, A2.w, off);
            A3.x += __shfl_xor_sync(0xFFFFFFFFu, A3.x, off);
            A3.y += __shfl_xor_sync(0xFFFFFFFFu, A3.y, off);
            A3.z += __shfl_xor_sync(0xFFFFFFFFu, A3.z, off);
            A3.w += __shfl_xor_sync(0xFFFFFFFFu, A3.w, off);
        }
        if (valid && o < 4) {                  // lanes 0-3 of oct write quads
            float4 v = (o == 0) ? A0 : (o == 1) ? A1 : (o == 2) ? A2 : A3;
            ((float4*)(g_g + (size_t)n * F_OUT))[o] = v;
        }
    } else if (role < 18) {                    // ---- DEGREE role (proven) --
        int deg_id = gid * 2 + (role - 16);    // 0..781
        int e = deg_id * 128 + tid;
#pragma unroll 4
        for (; e < N_EDGES; e += DEG_STRIDE) {
            int c = dst[e];
            atomicAdd(&g_deg[c], 1);
        }
    } else {                                   // ---- ZERO role (proven) ----
        const float4 z4 = make_float4(0.f, 0.f, 0.f, 0.f);
        for (int i = gid * 128 + tid; i < N_NODES * F_OUT / 4;
             i += ZERO_IDS * 128)
            ((float4*)g_acc)[i] = z4;
        if (gid == 0 && tid < F_OUT) out[tid] = 0.0f;
    }
}

// ---------------- K2: dinv v2 (R11-proven) + PDL sync ----------------------
__global__ void __launch_bounds__(256) k_dinv() {
    cudaGridDependencySynchronize();           // wait for k_fused results
    int t = blockIdx.x * 256 + threadIdx.x;
    int n = t >> 2;
    int q = t & 3;
    if (n >= N_NODES) return;
    float dv = rsqrtf((float)(g_deg[n] + 1));  // +1 self loop
    if (q == 0) {
        g_dinv[n] = dv;
        g_deg[n] = 0;                          // restore invariant for replay
    }
    float4* gg = (float4*)g_g + n * 4 + q;
    float4 v = *gg;
    *gg = make_float4(v.x * dv, v.y * dv, v.z * dv, v.w * dv);
}

// ---------------- K3: scatter (R2-proven core) + PDL index prefetch --------
__global__ void __launch_bounds__(256) k_scatter(const int* __restrict__ src,
                                                 const int* __restrict__ dst) {
    long long t = (long long)blockIdx.x * blockDim.x + threadIdx.x;
    int e = (int)(t >> 2);
    int q = (int)(t & 3);
    if (e >= N_EDGES) {
        cudaGridDependencySynchronize();
        return;
    }
    int r = src[e];
    int c = dst[e];
    cudaGridDependencySynchronize();           // wait for k_dinv (g scaled)
    float4 v = ((const float4*)g_g)[r * 4 + q];
    float* p = g_acc + (size_t)c * F_OUT + q * 4;
    asm volatile("red.global.add.v4.f32 [%0], {%1,%2,%3,%4};"
                 :: "l"(p), "f"(v.x), "f"(v.y), "f"(v.z), "f"(v.w)
                 : "memory");
}

// ---------------- K4: finalize v2 (R10-proven) + PDL prefetch --------------
#define FIN_TPB    256
#define FIN_BLOCKS ((4 * N_NODES + FIN_TPB - 1) / FIN_TPB)   // 1563

__global__ void __launch_bounds__(FIN_TPB) k_finalize(const float* __restrict__ b,
                                                      float* __restrict__ out) {
    __shared__ float sm[F_OUT];
    if (threadIdx.x < F_OUT) sm[threadIdx.x] = 0.f;

    int t = blockIdx.x * FIN_TPB + threadIdx.x;
    int n = t >> 2;
    int q = t & 3;
    int lane = threadIdx.x & 31;

    float dv = 0.f;
    float4 g = make_float4(0.f, 0.f, 0.f, 0.f);
    float4 bb = g;
    if (n < N_NODES) {
        dv = g_dinv[n];
        g  = ((const float4*)g_g)[n * 4 + q];
        bb = ((const float4*)b)[q];
    }
    cudaGridDependencySynchronize();           // wait for k_scatter (acc)
    __syncthreads();

    float4 r = make_float4(0.f, 0.f, 0.f, 0.f);
    if (n < N_NODES) {
        float4 a = ((const float4*)g_acc)[n * 4 + q];
        r.x = tanhf(dv * (a.x + g.x) + bb.x);
        r.y = tanhf(dv * (a.y + g.y) + bb.y);
        r.z = tanhf(dv * (a.z + g.z) + bb.z);
        r.w = tanhf(dv * (a.w + g.w) + bb.w);
    }

#pragma unroll
    for (int off = 16; off >= 4; off >>= 1) {
        r.x += __shfl_xor_sync(0xFFFFFFFFu, r.x, off);
        r.y += __shfl_xor_sync(0xFFFFFFFFu, r.y, off);
        r.z += __shfl_xor_sync(0xFFFFFFFFu, r.z, off);
        r.w += __shfl_xor_sync(0xFFFFFFFFu, r.w, off);
    }
    if (lane < 4) {
        atomicAdd(&sm[lane * 4 + 0], r.x);
        atomicAdd(&sm[lane * 4 + 1], r.y);
        atomicAdd(&sm[lane * 4 + 2], r.z);
        atomicAdd(&sm[lane * 4 + 3], r.w);
    }
    __syncthreads();
    if (threadIdx.x < F_OUT)
        atomicAdd(&out[threadIdx.x], sm[threadIdx.x] * (1.0f / (float)N_NODES));
}

// ---------------- launch (PDL chain) ----------------------------------------
static void launch_pdl(void* func, dim3 grid, dim3 block,
                       void** args, cudaStream_t stream) {
    cudaLaunchAttribute attr[1];
    attr[0].id = cudaLaunchAttributeProgrammaticStreamSerialization;
    attr[0].val.programmaticStreamSerializationAllowed = 1;
    cudaLaunchConfig_t cfg;
    cfg.gridDim = grid;
    cfg.blockDim = block;
    cfg.dynamicSmemBytes = 0;
    cfg.stream = stream;
    cfg.attrs = attr;
    cfg.numAttrs = 1;
    cudaLaunchKernelExC(&cfg, func, args);
}

extern "C" void kernel_launch(void* const* d_in, const int* in_sizes, int n_in,
                              void* d_out, int out_size) {
    const float* x  = (const float*)d_in[0];
    const int*   ei = (const int*)d_in[1];   // [2, N_EDGES] int32 (JAX x64 off)
    const float* W  = (const float*)d_in[2];
    const float* b  = (const float*)d_in[3];
    float*       out = (float*)d_out;

    const int* src = ei;
    const int* dst = ei + N_EDGES;

    k_fused<<<FUSED_BLOCKS, 128>>>(x, W, dst, out);

    {   // dinv: PDL after fused
        void* args[] = {};
        launch_pdl((void*)k_dinv, dim3((4 * N_NODES + 255) / 256), dim3(256),
                   args, 0);
    }
    {   // scatter: PDL after dinv
        long long threads = (long long)N_EDGES * 4;
        void* args[] = {(void*)&src, (void*)&dst};
        launch_pdl((void*)k_scatter, dim3((int)((threads + 255) / 256)),
                   dim3(256), args, 0);
    }
    {   // finalize: PDL after scatter
        void* args[] = {(void*)&b, (void*)&out};
        launch_pdl((void*)k_finalize, dim3(FIN_BLOCKS), dim3(FIN_TPB), args, 0);
    }
}

// round 15
// speedup vs baseline: 1.0908x; 1.0390x over previous
#include <cuda_runtime.h>
#include <math.h>

#define N_NODES 100000
#define N_EDGES 6400000
#define F_IN    128
#define F_OUT   16

// ------------- device scratch (zero-init; invariants restored per call) ---
__device__ int   g_deg [N_NODES];            // in-deg from 0; k_dinv resets
__device__ float g_dinv[N_NODES];            // rsqrt(deg+1)
__device__ float g_g   [N_NODES * F_OUT];    // h=x@W (unscaled), then *dinv
__device__ float g_acc [N_NODES * F_OUT];    // scatter acc; zeroed in fused

// ---------------- K1: fused  gemm(h) || degree || zero ---------------------
// role = blockIdx%11: <8 gemm (3125 ids, 32 nodes each, 2 nodes/lane,
// warp-coalesced), <10 degree (782 ids, proven), ==10 zero (391 ids).
#define GEMM_IDS 3125                          // 3125 * 32 == N_NODES exactly
#define DEG_IDS  782
#define ZERO_IDS 391
#define FUSED_BLOCKS (11 * 391)                // 4301
#define DEG_STRIDE (DEG_IDS * 128)             // 100096 threads

__global__ void __launch_bounds__(128) k_fused(const float* __restrict__ x,
                                               const float* __restrict__ W,
                                               const int* __restrict__ dst,
                                               float* __restrict__ out) {
    __shared__ float4 Ws4[F_IN * F_OUT / 4];   // XOR-swizzled W quads
    int role = blockIdx.x % 11;
    int gid  = blockIdx.x / 11;
    int tid  = threadIdx.x;

    if (role < 8) {                            // ---- GEMM role ----
        int gemm_id = gid * 8 + role;          // 0..3127 (3 tail ids idle)
        for (int i = tid; i < F_IN * F_OUT / 4; i += 128)
            Ws4[i ^ ((i >> 4) & 7)] = ((const float4*)W)[i];
        __syncthreads();
        if (gemm_id >= GEMM_IDS) return;

        int lane = tid & 31;
        int o    = lane & 7;                   // K-eighth (16 k's)
        int nw   = lane >> 3;                  // node slot (0..3)
        int base = gemm_id * 32 + (tid >> 5) * 8;
        int n0   = base + nw;                  // nodes base..base+3
        int n1   = n0 + 4;                     // nodes base+4..base+7

        const float4* xa = (const float4*)(x + (size_t)n0 * F_IN);
        const float4* xb = (const float4*)(x + (size_t)n1 * F_IN);

        float4 A0 = make_float4(0.f, 0.f, 0.f, 0.f);
        float4 A1 = A0, A2 = A0, A3 = A0;
        float4 C0 = A0, C1 = A0, C2 = A0, C3 = A0;

#pragma unroll
        for (int i = 0; i < 4; i++) {
            float4 xva = xa[i * 8 + o];        // 8 lanes -> one 128B line
            float4 xvb = xb[i * 8 + o];
#pragma unroll
            for (int j = 0; j < 4; j++) {
                float pa = (j == 0) ? xva.x : (j == 1) ? xva.y
                         : (j == 2) ? xva.z : xva.w;
                float pb = (j == 0) ? xvb.x : (j == 1) ? xvb.y
                         : (j == 2) ? xvb.z : xvb.w;
                int bq = (i * 32 + o * 4 + j) * 4;     // quad index of row k
                float4 w0 = Ws4[(bq + 0) ^ o];         // bank-disjoint
                float4 w1 = Ws4[(bq + 1) ^ o];
                float4 w2 = Ws4[(bq + 2) ^ o];
                float4 w3 = Ws4[(bq + 3) ^ o];
                A0.x += pa * w0.x; A0.y += pa * w0.y;
                A0.z += pa * w0.z; A0.w += pa * w0.w;
                A1.x += pa * w1.x; A1.y += pa * w1.y;
                A1.z += pa * w1.z; A1.w += pa * w1.w;
                A2.x += pa * w2.x; A2.y += pa * w2.y;
                A2.z += pa * w2.z; A2.w += pa * w2.w;
                A3.x += pa * w3.x; A3.y += pa * w3.y;
                A3.z += pa * w3.z; A3.w += pa * w3.w;
                C0.x += pb * w0.x; C0.y += pb * w0.y;
                C0.z += pb * w0.z; C0.w += pb * w0.w;
                C1.x += pb * w1.x; C1.y += pb * w1.y;
                C1.z += pb * w1.z; C1.w += pb * w1.w;
                C2.x += pb * w2.x; C2.y += pb * w2.y;
                C2.z += pb * w2.z; C2.w += pb * w2.w;
                C3.x += pb * w3.x; C3.y += pb * w3.y;
                C3.z += pb * w3.z; C3.w += pb * w3.w;
            }
        }
        // reduce over the 8 K-eighths (lane bits 0..2), both node sets
#pragma unroll
        for (int off = 1; off <= 4; off <<= 1) {
            A0.x += __shfl_xor_sync(0xFFFFFFFFu, A0.x, off);
            A0.y += __shfl_xor_sync(0xFFFFFFFFu, A0.y, off);
            A0.z += __shfl_xor_sync(0xFFFFFFFFu, A0.z, off);
            A0.w += __shfl_xor_sync(0xFFFFFFFFu, A0.w, off);
            A1.x += __shfl_xor_sync(0xFFFFFFFFu, A1.x, off);
            A1.y += __shfl_xor_sync(0xFFFFFFFFu, A1.y, off);
            A1.z += __shfl_xor_sync(0xFFFFFFFFu, A1.z, off);
            A1.w += __shfl_xor_sync(0xFFFFFFFFu, A1.w, off);
            A2.x += __shfl_xor_sync(0xFFFFFFFFu, A2.x, off);
            A2.y += __shfl_xor_sync(0xFFFFFFFFu, A2.y, off);
            A2.z += __shfl_xor_sync(0xFFFFFFFFu, A2.z, off);
            A2.w += __shfl_xor_sync(0xFFFFFFFFu, A2.w, off);
            A3.x += __shfl_xor_sync(0xFFFFFFFFu, A3.x, off);
            A3.y += __shfl_xor_sync(0xFFFFFFFFu, A3.y, off);
            A3.z += __shfl_xor_sync(0xFFFFFFFFu, A3.z, off);
            A3.w += __shfl_xor_sync(0xFFFFFFFFu, A3.w, off);
            C0.x += __shfl_xor_sync(0xFFFFFFFFu, C0.x, off);
            C0.y += __shfl_xor_sync(0xFFFFFFFFu, C0.y, off);
            C0.z += __shfl_xor_sync(0xFFFFFFFFu, C0.z, off);
            C0.w += __shfl_xor_sync(0xFFFFFFFFu, C0.w, off);
            C1.x += __shfl_xor_sync(0xFFFFFFFFu, C1.x, off);
            C1.y += __shfl_xor_sync(0xFFFFFFFFu, C1.y, off);
            C1.z += __shfl_xor_sync(0xFFFFFFFFu, C1.z, off);
            C1.w += __shfl_xor_sync(0xFFFFFFFFu, C1.w, off);
            C2.x += __shfl_xor_sync(0xFFFFFFFFu, C2.x, off);
            C2.y += __shfl_xor_sync(0xFFFFFFFFu, C2.y, off);
            C2.z += __shfl_xor_sync(0xFFFFFFFFu, C2.z, off);
            C2.w += __shfl_xor_sync(0xFFFFFFFFu, C2.w, off);
            C3.x += __shfl_xor_sync(0xFFFFFFFFu, C3.x, off);
            C3.y += __shfl_xor_sync(0xFFFFFFFFu, C3.y, off);
            C3.z += __shfl_xor_sync(0xFFFFFFFFu, C3.z, off);
            C3.w += __shfl_xor_sync(0xFFFFFFFFu, C3.w, off);
        }
        // lanes o<4 write node n0's quad o; lanes o>=4 write n1's quad o-4
        {
            int n = (o < 4) ? n0 : n1;
            int qidx = o & 3;
            float4 v;
            if (o < 4)
                v = (qidx == 0) ? A0 : (qidx == 1) ? A1 : (qidx == 2) ? A2 : A3;
            else
                v = (qidx == 0) ? C0 : (qidx == 1) ? C1 : (qidx == 2) ? C2 : C3;
            ((float4*)(g_g + (size_t)n * F_OUT))[qidx] = v;
        }
    } else if (role < 10) {                    // ---- DEGREE role (proven) --
        int deg_id = gid * 2 + (role - 8);     // 0..781
        int e = deg_id * 128 + tid;
#pragma unroll 4
        for (; e < N_EDGES; e += DEG_STRIDE) {
            int c = dst[e];
            atomicAdd(&g_deg[c], 1);
        }
    } else {                                   // ---- ZERO role (proven) ----
        const float4 z4 = make_float4(0.f, 0.f, 0.f, 0.f);
        for (int i = gid * 128 + tid; i < N_NODES * F_OUT / 4;
             i += ZERO_IDS * 128)
            ((float4*)g_acc)[i] = z4;
        if (gid == 0 && tid < F_OUT) out[tid] = 0.0f;
    }
}

// ---------------- K2: dinv v2 (R11-proven) + PDL sync ----------------------
__global__ void __launch_bounds__(256) k_dinv() {
    cudaGridDependencySynchronize();           // wait for k_fused results
    int t = blockIdx.x * 256 + threadIdx.x;
    int n = t >> 2;
    int q = t & 3;
    if (n >= N_NODES) return;
    float dv = rsqrtf((float)(g_deg[n] + 1));  // +1 self loop
    if (q == 0) {
        g_dinv[n] = dv;
        g_deg[n] = 0;                          // restore invariant for replay
    }
    float4* gg = (float4*)g_g + n * 4 + q;
    float4 v = *gg;
    *gg = make_float4(v.x * dv, v.y * dv, v.z * dv, v.w * dv);
}

// ---------------- K3: scatter (R2-proven core) + PDL index prefetch --------
__global__ void __launch_bounds__(256) k_scatter(const int* __restrict__ src,
                                                 const int* __restrict__ dst) {
    long long t = (long long)blockIdx.x * blockDim.x + threadIdx.x;
    int e = (int)(t >> 2);
    int q = (int)(t & 3);
    if (e >= N_EDGES) {
        cudaGridDependencySynchronize();
        return;
    }
    int r = src[e];
    int c = dst[e];
    cudaGridDependencySynchronize();           // wait for k_dinv (g scaled)
    float4 v = ((const float4*)g_g)[r * 4 + q];
    float* p = g_acc + (size_t)c * F_OUT + q * 4;
    asm volatile("red.global.add.v4.f32 [%0], {%1,%2,%3,%4};"
                 :: "l"(p), "f"(v.x), "f"(v.y), "f"(v.z), "f"(v.w)
                 : "memory");
}

// ---------------- K4: finalize v2 (R10-proven) + PDL prefetch --------------
#define FIN_TPB    256
#define FIN_BLOCKS ((4 * N_NODES + FIN_TPB - 1) / FIN_TPB)   // 1563

__global__ void __launch_bounds__(FIN_TPB) k_finalize(const float* __restrict__ b,
                                                      float* __restrict__ out) {
    __shared__ float sm[F_OUT];
    if (threadIdx.x < F_OUT) sm[threadIdx.x] = 0.f;

    int t = blockIdx.x * FIN_TPB + threadIdx.x;
    int n = t >> 2;
    int q = t & 3;
    int lane = threadIdx.x & 31;

    float dv = 0.f;
    float4 g = make_float4(0.f, 0.f, 0.f, 0.f);
    float4 bb = g;
    if (n < N_NODES) {
        dv = g_dinv[n];
        g  = ((const float4*)g_g)[n * 4 + q];
        bb = ((const float4*)b)[q];
    }
    cudaGridDependencySynchronize();           // wait for k_scatter (acc)
    __syncthreads();

    float4 r = make_float4(0.f, 0.f, 0.f, 0.f);
    if (n < N_NODES) {
        float4 a = ((const float4*)g_acc)[n * 4 + q];
        r.x = tanhf(dv * (a.x + g.x) + bb.x);
        r.y = tanhf(dv * (a.y + g.y) + bb.y);
        r.z = tanhf(dv * (a.z + g.z) + bb.z);
        r.w = tanhf(dv * (a.w + g.w) + bb.w);
    }

#pragma unroll
    for (int off = 16; off >= 4; off >>= 1) {
        r.x += __shfl_xor_sync(0xFFFFFFFFu, r.x, off);
        r.y += __shfl_xor_sync(0xFFFFFFFFu, r.y, off);
        r.z += __shfl_xor_sync(0xFFFFFFFFu, r.z, off);
        r.w += __shfl_xor_sync(0xFFFFFFFFu, r.w, off);
    }
    if (lane < 4) {
        atomicAdd(&sm[lane * 4 + 0], r.x);
        atomicAdd(&sm[lane * 4 + 1], r.y);
        atomicAdd(&sm[lane * 4 + 2], r.z);
        atomicAdd(&sm[lane * 4 + 3], r.w);
    }
    __syncthreads();
    if (threadIdx.x < F_OUT)
        atomicAdd(&out[threadIdx.x], sm[threadIdx.x] * (1.0f / (float)N_NODES));
}

// ---------------- launch (PDL chain) ----------------------------------------
static void launch_pdl(void* func, dim3 grid, dim3 block,
                       void** args, cudaStream_t stream) {
    cudaLaunchAttribute attr[1];
    attr[0].id = cudaLaunchAttributeProgrammaticStreamSerialization;
    attr[0].val.programmaticStreamSerializationAllowed = 1;
    cudaLaunchConfig_t cfg;
    cfg.gridDim = grid;
    cfg.blockDim = block;
    cfg.dynamicSmemBytes = 0;
    cfg.stream = stream;
    cfg.attrs = attr;
    cfg.numAttrs = 1;
    cudaLaunchKernelExC(&cfg, func, args);
}

extern "C" void kernel_launch(void* const* d_in, const int* in_sizes, int n_in,
                              void* d_out, int out_size) {
    const float* x  = (const float*)d_in[0];
    const int*   ei = (const int*)d_in[1];   // [2, N_EDGES] int32 (JAX x64 off)
    const float* W  = (const float*)d_in[2];
    const float* b  = (const float*)d_in[3];
    float*       out = (float*)d_out;

    const int* src = ei;
    const int* dst = ei + N_EDGES;

    k_fused<<<FUSED_BLOCKS, 128>>>(x, W, dst, out);

    {   // dinv: PDL after fused
        void* args[] = {};
        launch_pdl((void*)k_dinv, dim3((4 * N_NODES + 255) / 256), dim3(256),
                   args, 0);
    }
    {   // scatter: PDL after dinv
        long long threads = (long long)N_EDGES * 4;
        void* args[] = {(void*)&src, (void*)&dst};
        launch_pdl((void*)k_scatter, dim3((int)((threads + 255) / 256)),
                   dim3(256), args, 0);
    }
    {   // finalize: PDL after scatter
        void* args[] = {(void*)&b, (void*)&out};
        launch_pdl((void*)k_finalize, dim3(FIN_BLOCKS), dim3(FIN_TPB), args, 0);
    }
}

// round 16
// speedup vs baseline: 1.1081x; 1.0158x over previous
#include <cuda_runtime.h>
#include <math.h>

#define N_NODES 100000
#define N_EDGES 6400000
#define F_IN    128
#define F_OUT   16

// ------------- device scratch (zero-init; invariants restored per call) ---
__device__ int   g_deg [N_NODES];            // in-deg from 0; k_dinv resets
__device__ float g_dinv[N_NODES];            // rsqrt(deg+1)
__device__ float g_g   [N_NODES * F_OUT];    // h=x@W (unscaled), then *dinv
__device__ float g_acc [N_NODES * F_OUT];    // scatter acc; zeroed in fused

// ---------------- K1: fused  gemm(h) || degree || zero ---------------------
// role = blockIdx%7: <4 gemm (1564 ids, 64 nodes each, 4 nodes/lane,
// warp-coalesced), <6 degree (782 ids, proven), ==6 zero (391 ids).
#define GEMM_IDS 1564                          // 1564*64 = 100096 >= N_NODES
#define DEG_IDS  782
#define ZERO_IDS 391
#define FUSED_BLOCKS (7 * 391)                 // 2737
#define DEG_STRIDE (DEG_IDS * 128)             // 100096 threads

__global__ void __launch_bounds__(128) k_fused(const float* __restrict__ x,
                                               const float* __restrict__ W,
                                               const int* __restrict__ dst,
                                               float* __restrict__ out) {
    __shared__ float4 Ws4[F_IN * F_OUT / 4];   // XOR-swizzled W quads
    int role = blockIdx.x % 7;
    int gid  = blockIdx.x / 7;
    int tid  = threadIdx.x;

    if (role < 4) {                            // ---- GEMM role ----
        int gemm_id = gid * 4 + role;          // 0..1563
        for (int i = tid; i < F_IN * F_OUT / 4; i += 128)
            Ws4[i ^ ((i >> 4) & 7)] = ((const float4*)W)[i];
        __syncthreads();

        int lane = tid & 31;
        int o    = lane & 7;                   // K-eighth (16 k's)
        int nw   = lane >> 3;                  // node slot (0..3)
        int base = gemm_id * 64 + (tid >> 5) * 16;   // 16 nodes per warp
        int n0 = base + nw;                    // set 0
        int n1 = n0 + 4;                       // set 1
        int n2 = n0 + 8;                       // set 2
        int n3 = n0 + 12;                      // set 3
        int c0 = min(n0, N_NODES - 1), c1 = min(n1, N_NODES - 1);
        int c2 = min(n2, N_NODES - 1), c3 = min(n3, N_NODES - 1);

        const float4* xa = (const float4*)(x + (size_t)c0 * F_IN);
        const float4* xb = (const float4*)(x + (size_t)c1 * F_IN);
        const float4* xc = (const float4*)(x + (size_t)c2 * F_IN);
        const float4* xd = (const float4*)(x + (size_t)c3 * F_IN);

        float4 A0 = make_float4(0.f, 0.f, 0.f, 0.f);
        float4 A1 = A0, A2 = A0, A3 = A0;
        float4 C0 = A0, C1 = A0, C2 = A0, C3 = A0;
        float4 E0 = A0, E1 = A0, E2 = A0, E3 = A0;
        float4 G0 = A0, G1 = A0, G2 = A0, G3 = A0;

#pragma unroll
        for (int i = 0; i < 4; i++) {
            float4 xva = xa[i * 8 + o];        // 8 lanes -> one 128B line
            float4 xvb = xb[i * 8 + o];
            float4 xvc = xc[i * 8 + o];
            float4 xvd = xd[i * 8 + o];
#pragma unroll
            for (int j = 0; j < 4; j++) {
                float pa = (j == 0) ? xva.x : (j == 1) ? xva.y
                         : (j == 2) ? xva.z : xva.w;
                float pb = (j == 0) ? xvb.x : (j == 1) ? xvb.y
                         : (j == 2) ? xvb.z : xvb.w;
                float pc = (j == 0) ? xvc.x : (j == 1) ? xvc.y
                         : (j == 2) ? xvc.z : xvc.w;
                float pd = (j == 0) ? xvd.x : (j == 1) ? xvd.y
                         : (j == 2) ? xvd.z : xvd.w;
                int bq = (i * 32 + o * 4 + j) * 4;     // quad index of row k
                float4 w0 = Ws4[(bq + 0) ^ o];         // bank-disjoint
                float4 w1 = Ws4[(bq + 1) ^ o];
                float4 w2 = Ws4[(bq + 2) ^ o];
                float4 w3 = Ws4[(bq + 3) ^ o];
                A0.x += pa * w0.x; A0.y += pa * w0.y;
                A0.z += pa * w0.z; A0.w += pa * w0.w;
                A1.x += pa * w1.x; A1.y += pa * w1.y;
                A1.z += pa * w1.z; A1.w += pa * w1.w;
                A2.x += pa * w2.x; A2.y += pa * w2.y;
                A2.z += pa * w2.z; A2.w += pa * w2.w;
                A3.x += pa * w3.x; A3.y += pa * w3.y;
                A3.z += pa * w3.z; A3.w += pa * w3.w;
                C0.x += pb * w0.x; C0.y += pb * w0.y;
                C0.z += pb * w0.z; C0.w += pb * w0.w;
                C1.x += pb * w1.x; C1.y += pb * w1.y;
                C1.z += pb * w1.z; C1.w += pb * w1.w;
                C2.x += pb * w2.x; C2.y += pb * w2.y;
                C2.z += pb * w2.z; C2.w += pb * w2.w;
                C3.x += pb * w3.x; C3.y += pb * w3.y;
                C3.z += pb * w3.z; C3.w += pb * w3.w;
                E0.x += pc * w0.x; E0.y += pc * w0.y;
                E0.z += pc * w0.z; E0.w += pc * w0.w;
                E1.x += pc * w1.x; E1.y += pc * w1.y;
                E1.z += pc * w1.z; E1.w += pc * w1.w;
                E2.x += pc * w2.x; E2.y += pc * w2.y;
                E2.z += pc * w2.z; E2.w += pc * w2.w;
                E3.x += pc * w3.x; E3.y += pc * w3.y;
                E3.z += pc * w3.z; E3.w += pc * w3.w;
                G0.x += pd * w0.x; G0.y += pd * w0.y;
                G0.z += pd * w0.z; G0.w += pd * w0.w;
                G1.x += pd * w1.x; G1.y += pd * w1.y;
                G1.z += pd * w1.z; G1.w += pd * w1.w;
                G2.x += pd * w2.x; G2.y += pd * w2.y;
                G2.z += pd * w2.z; G2.w += pd * w2.w;
                G3.x += pd * w3.x; G3.y += pd * w3.y;
                G3.z += pd * w3.z; G3.w += pd * w3.w;
            }
        }
        // reduce over the 8 K-eighths (lane bits 0..2), all four node sets
#pragma unroll
        for (int off = 1; off <= 4; off <<= 1) {
            A0.x += __shfl_xor_sync(0xFFFFFFFFu, A0.x, off);
            A0.y += __shfl_xor_sync(0xFFFFFFFFu, A0.y, off);
            A0.z += __shfl_xor_sync(0xFFFFFFFFu, A0.z, off);
            A0.w += __shfl_xor_sync(0xFFFFFFFFu, A0.w, off);
            A1.x += __shfl_xor_sync(0xFFFFFFFFu, A1.x, off);
            A1.y += __shfl_xor_sync(0xFFFFFFFFu, A1.y, off);
            A1.z += __shfl_xor_sync(0xFFFFFFFFu, A1.z, off);
            A1.w += __shfl_xor_sync(0xFFFFFFFFu, A1.w, off);
            A2.x += __shfl_xor_sync(0xFFFFFFFFu, A2.x, off);
            A2.y += __shfl_xor_sync(0xFFFFFFFFu, A2.y, off);
            A2.z += __shfl_xor_sync(0xFFFFFFFFu, A2.z, off);
            A2.w += __shfl_xor_sync(0xFFFFFFFFu, A2.w, off);
            A3.x += __shfl_xor_sync(0xFFFFFFFFu, A3.x, off);
            A3.y += __shfl_xor_sync(0xFFFFFFFFu, A3.y, off);
            A3.z += __shfl_xor_sync(0xFFFFFFFFu, A3.z, off);
            A3.w += __shfl_xor_sync(0xFFFFFFFFu, A3.w, off);
            C0.x += __shfl_xor_sync(0xFFFFFFFFu, C0.x, off);
            C0.y += __shfl_xor_sync(0xFFFFFFFFu, C0.y, off);
            C0.z += __shfl_xor_sync(0xFFFFFFFFu, C0.z, off);
            C0.w += __shfl_xor_sync(0xFFFFFFFFu, C0.w, off);
            C1.x += __shfl_xor_sync(0xFFFFFFFFu, C1.x, off);
            C1.y += __shfl_xor_sync(0xFFFFFFFFu, C1.y, off);
            C1.z += __shfl_xor_sync(0xFFFFFFFFu, C1.z, off);
            C1.w += __shfl_xor_sync(0xFFFFFFFFu, C1.w, off);
            C2.x += __shfl_xor_sync(0xFFFFFFFFu, C2.x, off);
            C2.y += __shfl_xor_sync(0xFFFFFFFFu, C2.y, off);
            C2.z += __shfl_xor_sync(0xFFFFFFFFu, C2.z, off);
            C2.w += __shfl_xor_sync(0xFFFFFFFFu, C2.w, off);
            C3.x += __shfl_xor_sync(0xFFFFFFFFu, C3.x, off);
            C3.y += __shfl_xor_sync(0xFFFFFFFFu, C3.y, off);
            C3.z += __shfl_xor_sync(0xFFFFFFFFu, C3.z, off);
            C3.w += __shfl_xor_sync(0xFFFFFFFFu, C3.w, off);
            E0.x += __shfl_xor_sync(0xFFFFFFFFu, E0.x, off);
            E0.y += __shfl_xor_sync(0xFFFFFFFFu, E0.y, off);
            E0.z += __shfl_xor_sync(0xFFFFFFFFu, E0.z, off);
            E0.w += __shfl_xor_sync(0xFFFFFFFFu, E0.w, off);
            E1.x += __shfl_xor_sync(0xFFFFFFFFu, E1.x, off);
            E1.y += __shfl_xor_sync(0xFFFFFFFFu, E1.y, off);
            E1.z += __shfl_xor_sync(0xFFFFFFFFu, E1.z, off);
            E1.w += __shfl_xor_sync(0xFFFFFFFFu, E1.w, off);
            E2.x += __shfl_xor_sync(0xFFFFFFFFu, E2.x, off);
            E2.y += __shfl_xor_sync(0xFFFFFFFFu, E2.y, off);
            E2.z += __shfl_xor_sync(0xFFFFFFFFu, E2.z, off);
            E2.w += __shfl_xor_sync(0xFFFFFFFFu, E2.w, off);
            E3.x += __shfl_xor_sync(0xFFFFFFFFu, E3.x, off);
            E3.y += __shfl_xor_sync(0xFFFFFFFFu, E3.y, off);
            E3.z += __shfl_xor_sync(0xFFFFFFFFu, E3.z, off);
            E3.w += __shfl_xor_sync(0xFFFFFFFFu, E3.w, off);
            G0.x += __shfl_xor_sync(0xFFFFFFFFu, G0.x, off);
            G0.y += __shfl_xor_sync(0xFFFFFFFFu, G0.y, off);
            G0.z += __shfl_xor_sync(0xFFFFFFFFu, G0.z, off);
            G0.w += __shfl_xor_sync(0xFFFFFFFFu, G0.w, off);
            G1.x += __shfl_xor_sync(0xFFFFFFFFu, G1.x, off);
            G1.y += __shfl_xor_sync(0xFFFFFFFFu, G1.y, off);
            G1.z += __shfl_xor_sync(0xFFFFFFFFu, G1.z, off);
            G1.w += __shfl_xor_sync(0xFFFFFFFFu, G1.w, off);
            G2.x += __shfl_xor_sync(0xFFFFFFFFu, G2.x, off);
            G2.y += __shfl_xor_sync(0xFFFFFFFFu, G2.y, off);
            G2.z += __shfl_xor_sync(0xFFFFFFFFu, G2.z, off);
            G2.w += __shfl_xor_sync(0xFFFFFFFFu, G2.w, off);
            G3.x += __shfl_xor_sync(0xFFFFFFFFu, G3.x, off);
            G3.y += __shfl_xor_sync(0xFFFFFFFFu, G3.y, off);
            G3.z += __shfl_xor_sync(0xFFFFFFFFu, G3.z, off);
            G3.w += __shfl_xor_sync(0xFFFFFFFFu, G3.w, off);
        }
        // lanes o<4 store sets 0&2; lanes o>=4 store sets 1&3 (quad o&3)
        {
            int qidx = o & 3;
            int na = (o < 4) ? n0 : n1;        // set 0 or 1
            int nb = (o < 4) ? n2 : n3;        // set 2 or 3
            float4 va, vb;
            if (o < 4) {
                va = (qidx == 0) ? A0 : (qidx == 1) ? A1 : (qidx == 2) ? A2 : A3;
                vb = (qidx == 0) ? E0 : (qidx == 1) ? E1 : (qidx == 2) ? E2 : E3;
            } else {
                va = (qidx == 0) ? C0 : (qidx == 1) ? C1 : (qidx == 2) ? C2 : C3;
                vb = (qidx == 0) ? G0 : (qidx == 1) ? G1 : (qidx == 2) ? G2 : G3;
            }
            if (na < N_NODES)
                ((float4*)(g_g + (size_t)na * F_OUT))[qidx] = va;
            if (nb < N_NODES)
                ((float4*)(g_g + (size_t)nb * F_OUT))[qidx] = vb;
        }
    } else if (role < 6) {                     // ---- DEGREE role (proven) --
        int deg_id = gid * 2 + (role - 4);     // 0..781
        int e = deg_id * 128 + tid;
#pragma unroll 4
        for (; e < N_EDGES; e += DEG_STRIDE) {
            int c = dst[e];
            atomicAdd(&g_deg[c], 1);
        }
    } else {                                   // ---- ZERO role (proven) ----
        const float4 z4 = make_float4(0.f, 0.f, 0.f, 0.f);
        for (int i = gid * 128 + tid; i < N_NODES * F_OUT / 4;
             i += ZERO_IDS * 128)
            ((float4*)g_acc)[i] = z4;
        if (gid == 0 && tid < F_OUT) out[tid] = 0.0f;
    }
}

// ---------------- K2: dinv v2 (R11-proven) + PDL sync ----------------------
__global__ void __launch_bounds__(256) k_dinv() {
    cudaGridDependencySynchronize();           // wait for k_fused results
    int t = blockIdx.x * 256 + threadIdx.x;
    int n = t >> 2;
    int q = t & 3;
    if (n >= N_NODES) return;
    float dv = rsqrtf((float)(g_deg[n] + 1));  // +1 self loop
    if (q == 0) {
        g_dinv[n] = dv;
        g_deg[n] = 0;                          // restore invariant for replay
    }
    float4* gg = (float4*)g_g + n * 4 + q;
    float4 v = *gg;
    *gg = make_float4(v.x * dv, v.y * dv, v.z * dv, v.w * dv);
}

// ---------------- K3: scatter (R2-proven core) + PDL index prefetch --------
__global__ void __launch_bounds__(256) k_scatter(const int* __restrict__ src,
                                                 const int* __restrict__ dst) {
    long long t = (long long)blockIdx.x * blockDim.x + threadIdx.x;
    int e = (int)(t >> 2);
    int q = (int)(t & 3);
    if (e >= N_EDGES) {
        cudaGridDependencySynchronize();
        return;
    }
    int r = src[e];
    int c = dst[e];
    cudaGridDependencySynchronize();           // wait for k_dinv (g scaled)
    float4 v = ((const float4*)g_g)[r * 4 + q];
    float* p = g_acc + (size_t)c * F_OUT + q * 4;
    asm volatile("red.global.add.v4.f32 [%0], {%1,%2,%3,%4};"
                 :: "l"(p), "f"(v.x), "f"(v.y), "f"(v.z), "f"(v.w)
                 : "memory");
}

// ---------------- K4: finalize v2 (R10-proven) + PDL prefetch --------------
#define FIN_TPB    256
#define FIN_BLOCKS ((4 * N_NODES + FIN_TPB - 1) / FIN_TPB)   // 1563

__global__ void __launch_bounds__(FIN_TPB) k_finalize(const float* __restrict__ b,
                                                      float* __restrict__ out) {
    __shared__ float sm[F_OUT];
    if (threadIdx.x < F_OUT) sm[threadIdx.x] = 0.f;

    int t = blockIdx.x * FIN_TPB + threadIdx.x;
    int n = t >> 2;
    int q = t & 3;
    int lane = threadIdx.x & 31;

    float dv = 0.f;
    float4 g = make_float4(0.f, 0.f, 0.f, 0.f);
    float4 bb = g;
    if (n < N_NODES) {
        dv = g_dinv[n];
        g  = ((const float4*)g_g)[n * 4 + q];
        bb = ((const float4*)b)[q];
    }
    cudaGridDependencySynchronize();           // wait for k_scatter (acc)
    __syncthreads();

    float4 r = make_float4(0.f, 0.f, 0.f, 0.f);
    if (n < N_NODES) {
        float4 a = ((const float4*)g_acc)[n * 4 + q];
        r.x = tanhf(dv * (a.x + g.x) + bb.x);
        r.y = tanhf(dv * (a.y + g.y) + bb.y);
        r.z = tanhf(dv * (a.z + g.z) + bb.z);
        r.w = tanhf(dv * (a.w + g.w) + bb.w);
    }

#pragma unroll
    for (int off = 16; off >= 4; off >>= 1) {
        r.x += __shfl_xor_sync(0xFFFFFFFFu, r.x, off);
        r.y += __shfl_xor_sync(0xFFFFFFFFu, r.y, off);
        r.z += __shfl_xor_sync(0xFFFFFFFFu, r.z, off);
        r.w += __shfl_xor_sync(0xFFFFFFFFu, r.w, off);
    }
    if (lane < 4) {
        atomicAdd(&sm[lane * 4 + 0], r.x);
        atomicAdd(&sm[lane * 4 + 1], r.y);
        atomicAdd(&sm[lane * 4 + 2], r.z);
        atomicAdd(&sm[lane * 4 + 3], r.w);
    }
    __syncthreads();
    if (threadIdx.x < F_OUT)
        atomicAdd(&out[threadIdx.x], sm[threadIdx.x] * (1.0f / (float)N_NODES));
}

// ---------------- launch (PDL chain) ----------------------------------------
static void launch_pdl(void* func, dim3 grid, dim3 block,
                       void** args, cudaStream_t stream) {
    cudaLaunchAttribute attr[1];
    attr[0].id = cudaLaunchAttributeProgrammaticStreamSerialization;
    attr[0].val.programmaticStreamSerializationAllowed = 1;
    cudaLaunchConfig_t cfg;
    cfg.gridDim = grid;
    cfg.blockDim = block;
    cfg.dynamicSmemBytes = 0;
    cfg.stream = stream;
    cfg.attrs = attr;
    cfg.numAttrs = 1;
    cudaLaunchKernelExC(&cfg, func, args);
}

extern "C" void kernel_launch(void* const* d_in, const int* in_sizes, int n_in,
                              void* d_out, int out_size) {
    const float* x  = (const float*)d_in[0];
    const int*   ei = (const int*)d_in[1];   // [2, N_EDGES] int32 (JAX x64 off)
    const float* W  = (const float*)d_in[2];
    const float* b  = (const float*)d_in[3];
    float*       out = (float*)d_out;

    const int* src = ei;
    const int* dst = ei + N_EDGES;

    k_fused<<<FUSED_BLOCKS, 128>>>(x, W, dst, out);

    {   // dinv: PDL after fused
        void* args[] = {};
        launch_pdl((void*)k_dinv, dim3((4 * N_NODES + 255) / 256), dim3(256),
                   args, 0);
    }
    {   // scatter: PDL after dinv
        long long threads = (long long)N_EDGES * 4;
        void* args[] = {(void*)&src, (void*)&dst};
        launch_pdl((void*)k_scatter, dim3((int)((threads + 255) / 256)),
                   dim3(256), args, 0);
    }
    {   // finalize: PDL after scatter
        void* args[] = {(void*)&b, (void*)&out};
        launch_pdl((void*)k_finalize, dim3(FIN_BLOCKS), dim3(FIN_TPB), args, 0);
    }
}